// round 15
// baseline (speedup 1.0000x reference)
#include <cuda_runtime.h>

// Attention_72447508349519 — algebraic collapse:
//   softmax rows sum to 1 and einsum('bqk,bvd->bqd') contracts k and v
//   independently, so out[b,q,d] = sum_n v[b,n,d] for every q.
//   Pipeline (R10 structure): k1 (stats+weighted colsums, __ldcs x) ->
//   k2 (fold) -> k3 (GEMV Wv) -> k4 (GEMV Wo + 64MB broadcast via __stwt).
//   R15: output stores are WRITE-THROUGH. With __stcs, only ~12MB of the
//   64MB output drained to DRAM inside k4 (DRAM=10% there); the other ~52MB
//   of dirty L2 drained during the NEXT replay's k1, serializing the
//   pipeline on deferred writeback. __stwt forces the drain into k4's own
//   window, where DRAM is ~90% idle.
// Unused inputs: Wq,bq,Wk,bk.

#define BSZ   16
#define CDIM  1024
#define NPOS  1024
#define NGRP  32
#define GROWS 32
#define EPS   1e-5f

__device__ float g_P[BSZ * NGRP * CDIM];
__device__ float g_mean[BSZ * NGRP];
__device__ float g_rstd[BSZ * NGRP];
__device__ float g_s[BSZ * CDIM];
__device__ float g_vsum[BSZ * CDIM];

// ---------------------------------------------------------------------------
// k1 (R10-proven): per (b,g) CTA, one pass over the 1024x32 slab of x.
// fj/gq lane mapping (every LDG.128 = 4 fully-used lines), MLP=8, 2 CTAs/SM.
// x loads / P stores streaming (evict-first) — R10's empirically best policy.
// ---------------------------------------------------------------------------
#define PPITCH 1028   // bank = (4*fj + gq) mod 32 -> all 32 lanes distinct

__global__ __launch_bounds__(512, 2) void k1_stats(const float* __restrict__ x,
                                                   const float* __restrict__ gamma) {
    const int b = blockIdx.x >> 5;
    const int g = blockIdx.x & 31;
    const int tid = threadIdx.x;

    __shared__ float sg[GROWS];
    __shared__ float spw[8 * PPITCH];
    __shared__ float reds[16], redq[16];

    if (tid < GROWS) sg[tid] = gamma[g * GROWS + tid];
    __syncthreads();

    const int fj = tid & 7;    // float4 slot within the 32-float group row
    const int gq = tid >> 3;   // channel base (c = gq + 64*k), 0..63
    const float w0 = sg[fj * 4 + 0], w1 = sg[fj * 4 + 1];
    const float w2 = sg[fj * 4 + 2], w3 = sg[fj * 4 + 3];

    const float* xb = x + (size_t)b * CDIM * NPOS + g * GROWS;
    float* mypw = spw + fj * PPITCH;

    float tsum = 0.f, tsq = 0.f;
    #pragma unroll
    for (int k0 = 0; k0 < 16; k0 += 8) {
        float4 t[8];
        #pragma unroll
        for (int i = 0; i < 8; i++) {
            const int c = gq + 64 * (k0 + i);
            t[i] = __ldcs(&reinterpret_cast<const float4*>(xb + (size_t)c * NPOS)[fj]);
        }
        #pragma unroll
        for (int i = 0; i < 8; i++) {
            const int c = gq + 64 * (k0 + i);
            const float4 v = t[i];
            tsum += (v.x + v.y) + (v.z + v.w);
            tsq  += (v.x * v.x + v.y * v.y) + (v.z * v.z + v.w * v.w);
            mypw[c] = w0 * v.x + w1 * v.y + w2 * v.z + w3 * v.w;
        }
    }
    __syncthreads();

    // Fold the 8 fj-partials per channel (conflict-free, stride-1 c).
    float* Pout = g_P + (b * NGRP + g) * CDIM;
    #pragma unroll
    for (int m = 0; m < 2; m++) {
        const int c = tid + 512 * m;
        float acc = spw[c];
        #pragma unroll
        for (int f = 1; f < 8; f++) acc += spw[f * PPITCH + c];
        __stcs(&Pout[c], acc);
    }

    // Block reduction for mean/rstd.
    #pragma unroll
    for (int o = 16; o; o >>= 1) {
        tsum += __shfl_xor_sync(0xFFFFFFFFu, tsum, o);
        tsq  += __shfl_xor_sync(0xFFFFFFFFu, tsq,  o);
    }
    const int wid = tid >> 5, lane = tid & 31;
    if (lane == 0) { reds[wid] = tsum; redq[wid] = tsq; }
    __syncthreads();
    if (tid == 0) {
        float S = 0.f, Q = 0.f;
        #pragma unroll
        for (int w = 0; w < 16; w++) { S += reds[w]; Q += redq[w]; }
        const float inv = 1.f / (float)(GROWS * CDIM);
        const float m = S * inv;
        const float var = Q * inv - m * m;
        g_mean[b * NGRP + g] = m;
        g_rstd[b * NGRP + g] = rsqrtf(var + EPS);
    }
}

// ---------------------------------------------------------------------------
// k2: s[b,c] = sum_g rstd[b,g]*(P[b,g,c] - mean[b,g]*Gam_g) + sum_n beta[n]
// ---------------------------------------------------------------------------
__global__ __launch_bounds__(1024) void k2_colsum(const float* __restrict__ gamma,
                                                  const float* __restrict__ beta) {
    const int b = blockIdx.x;
    const int tid = threadIdx.x;

    __shared__ float sgam[CDIM];
    __shared__ float sGam[NGRP];
    __shared__ float sm[NGRP], sr[NGRP];
    __shared__ float redb[32];
    __shared__ float sB;

    sgam[tid] = gamma[tid];
    float bb = beta[tid];
    #pragma unroll
    for (int o = 16; o; o >>= 1) bb += __shfl_xor_sync(0xFFFFFFFFu, bb, o);
    const int wid = tid >> 5, lane = tid & 31;
    if (lane == 0) redb[wid] = bb;
    if (tid < NGRP) { sm[tid] = g_mean[b * NGRP + tid]; sr[tid] = g_rstd[b * NGRP + tid]; }
    __syncthreads();

    if (tid < NGRP) {
        float t = 0.f;
        #pragma unroll
        for (int j = 0; j < GROWS; j++) t += sgam[tid * GROWS + j];
        sGam[tid] = t;
    }
    if (tid == 0) {
        float t = 0.f;
        #pragma unroll
        for (int w = 0; w < 32; w++) t += redb[w];
        sB = t;
    }
    __syncthreads();

    float acc = sB;
    const float* Pb = g_P + b * NGRP * CDIM + tid;
    #pragma unroll
    for (int g = 0; g < NGRP; g++)
        acc += sr[g] * (__ldcs(&Pb[g * CDIM]) - sm[g] * sGam[g]);
    g_s[b * CDIM + tid] = acc;
}

// ---------------------------------------------------------------------------
// k3: vsum[b,d] = s[b,:].Wv[d,:] + 1024*bv[d]
// grid (128 d-tiles, 8 batch-groups) = 1024 CTAs, 256 thr, 8KB smem.
// One warp per d, 2-batch accumulators; full W row batched into registers.
// ---------------------------------------------------------------------------
__global__ __launch_bounds__(256) void k3_gemv_v(const float* __restrict__ W,
                                                 const float* __restrict__ bias) {
    const int bg = blockIdx.y;           // batches 2*bg, 2*bg+1
    const int tid = threadIdx.x;
    const int wid = tid >> 5, lane = tid & 31;
    const int d = blockIdx.x * 8 + wid;

    __shared__ float ss[2 * CDIM];       // 8 KB

    const float4* wrow = reinterpret_cast<const float4*>(W + (size_t)d * CDIM);
    float4 wreg[8];
    #pragma unroll
    for (int j = 0; j < 8; j++) wreg[j] = wrow[lane + 32 * j];

    {
        const float4* src = reinterpret_cast<const float4*>(g_s + bg * 2 * CDIM);
        float4* dst = reinterpret_cast<float4*>(ss);
        #pragma unroll
        for (int m = 0; m < 2; m++) dst[tid + 256 * m] = src[tid + 256 * m];
    }
    __syncthreads();

    float acc[2] = {0.f, 0.f};
    #pragma unroll
    for (int j = 0; j < 8; j++) {
        const float4 wv = wreg[j];
        #pragma unroll
        for (int q = 0; q < 2; q++) {
            const float4 sv = reinterpret_cast<const float4*>(ss + q * CDIM)[lane + 32 * j];
            acc[q] += wv.x * sv.x + wv.y * sv.y + wv.z * sv.z + wv.w * sv.w;
        }
    }
    #pragma unroll
    for (int q = 0; q < 2; q++)
        #pragma unroll
        for (int o = 16; o; o >>= 1)
            acc[q] += __shfl_xor_sync(0xFFFFFFFFu, acc[q], o);

    if (lane == 0) {
        const float bs = (float)NPOS * bias[d];
        #pragma unroll
        for (int q = 0; q < 2; q++)
            g_vsum[(bg * 2 + q) * CDIM + d] = acc[q] + bs;
    }
}

// ---------------------------------------------------------------------------
// k4: y[b,d] = vsum[b,:].Wo[d,:] + bo[d], fused with the 64MB broadcast
// store out[b,d,:] = y[b,d] via __stwt (WRITE-THROUGH: drain to DRAM happens
// inside k4's window instead of being deferred into next replay's k1).
// grid (128, 8) = 1024 CTAs.
// ---------------------------------------------------------------------------
__global__ __launch_bounds__(256) void k4_gemv_o_bcast(const float* __restrict__ W,
                                                       const float* __restrict__ bias,
                                                       float* __restrict__ out) {
    const int bg = blockIdx.y;           // batches 2*bg, 2*bg+1
    const int tid = threadIdx.x;
    const int wid = tid >> 5, lane = tid & 31;
    const int d = blockIdx.x * 8 + wid;

    __shared__ float ss[2 * CDIM];       // 8 KB

    const float4* wrow = reinterpret_cast<const float4*>(W + (size_t)d * CDIM);
    float4 wreg[8];
    #pragma unroll
    for (int j = 0; j < 8; j++) wreg[j] = wrow[lane + 32 * j];

    {
        const float4* src = reinterpret_cast<const float4*>(g_vsum + bg * 2 * CDIM);
        float4* dst = reinterpret_cast<float4*>(ss);
        #pragma unroll
        for (int m = 0; m < 2; m++) dst[tid + 256 * m] = src[tid + 256 * m];
    }
    __syncthreads();

    float acc[2] = {0.f, 0.f};
    #pragma unroll
    for (int j = 0; j < 8; j++) {
        const float4 wv = wreg[j];
        #pragma unroll
        for (int q = 0; q < 2; q++) {
            const float4 sv = reinterpret_cast<const float4*>(ss + q * CDIM)[lane + 32 * j];
            acc[q] += wv.x * sv.x + wv.y * sv.y + wv.z * sv.z + wv.w * sv.w;
        }
    }
    // Butterfly: every lane ends with the full sum -> whole warp streams stores.
    #pragma unroll
    for (int q = 0; q < 2; q++)
        #pragma unroll
        for (int o = 16; o; o >>= 1)
            acc[q] += __shfl_xor_sync(0xFFFFFFFFu, acc[q], o);

    const float bs = bias[d];
    #pragma unroll
    for (int q = 0; q < 2; q++) {
        const float v = acc[q] + bs;
        const float4 vv = make_float4(v, v, v, v);
        float4* row = reinterpret_cast<float4*>(
            out + ((size_t)((bg * 2 + q) * CDIM + d)) * NPOS);
        #pragma unroll
        for (int t = 0; t < 8; t++) __stwt(&row[lane + 32 * t], vv);
    }
}

extern "C" void kernel_launch(void* const* d_in, const int* in_sizes, int n_in,
                              void* d_out, int out_size) {
    const float* x     = (const float*)d_in[0];
    const float* gamma = (const float*)d_in[1];
    const float* beta  = (const float*)d_in[2];
    // d_in[3..6] = Wq,bq,Wk,bk : provably unused (softmax rows sum to 1).
    const float* Wv    = (const float*)d_in[7];
    const float* bv    = (const float*)d_in[8];
    const float* Wo    = (const float*)d_in[9];
    const float* bo    = (const float*)d_in[10];
    float* out = (float*)d_out;

    k1_stats<<<BSZ * NGRP, 512>>>(x, gamma);
    k2_colsum<<<BSZ, 1024>>>(gamma, beta);
    k3_gemv_v<<<dim3(CDIM / 8, 8), 256>>>(Wv, bv);
    k4_gemv_o_bcast<<<dim3(CDIM / 8, 8), 256>>>(Wo, bo, out);
}